// round 12
// baseline (speedup 1.0000x reference)
#include <cuda_runtime.h>
#include <cuda_fp16.h>
#include <cstdint>
#include <math.h>

// ================= problem constants =================
#define NN    50000
#define EE    400000
#define GG    256
#define FIN   79
#define DD    400
#define BN_EPS 1e-5f

#define NMATS  7
#define WPITCH 416            // staged weight K pitch (halfs)
#define PITCH  416            // fp32 activation pitch (13 * 32)
#define XPITCH 96             // layer-1 fp32 pitch (3 * 32)
#define PKPITCH 1664          // packed activation row pitch in BYTES (26 groups * 64B)

// ================= scratch (device globals; zero-initialized) ============
__device__ float g_bufA[(size_t)NN * PITCH];
__device__ float g_bufB[(size_t)NN * PITCH];
__device__ float g_bufC[(size_t)NN * PITCH];
__device__ float g_xpad[(size_t)NN * XPITCH];
__device__ float g_z1[(size_t)NN * XPITCH];
__device__ __align__(16) uint32_t g_P0[(size_t)NN * (PKPITCH / 4)];
__device__ __align__(16) uint32_t g_P1[(size_t)NN * (PKPITCH / 4)];
__device__ __align__(16) __half g_Wh[(size_t)NMATS * DD * WPITCH];
__device__ float g_alpha1[DD], g_beta1[DD], g_alpha2[DD], g_beta2[DD];

// ================= helpers =================
__device__ __forceinline__ uint32_t smem_to_u32(const void* p) {
    uint32_t a;
    asm("{ .reg .u64 t; cvta.to.shared.u64 t, %1; cvt.u32.u64 %0, t; }"
        : "=r"(a) : "l"(p));
    return a;
}

__device__ __forceinline__ void cp16(uint32_t saddr, const void* gptr, bool valid) {
    int sz = valid ? 16 : 0;
    asm volatile("cp.async.cg.shared.global [%0], [%1], 16, %2;"
                 :: "r"(saddr), "l"(gptr), "r"(sz));
}
#define CP_COMMIT() asm volatile("cp.async.commit_group;")
#define CP_WAIT(n)  asm volatile("cp.async.wait_group %0;" :: "n"(n))

#define LDSM4(R, addr) \
    asm volatile("ldmatrix.sync.aligned.m8n8.x4.shared.b16 {%0,%1,%2,%3}, [%4];" \
        : "=r"((R)[0]), "=r"((R)[1]), "=r"((R)[2]), "=r"((R)[3]) : "r"(addr))

#define LDSM4P(r0, r1, r2, r3, addr) \
    asm volatile("ldmatrix.sync.aligned.m8n8.x4.shared.b16 {%0,%1,%2,%3}, [%4];" \
        : "=r"(r0), "=r"(r1), "=r"(r2), "=r"(r3) : "r"(addr))

#define LDSM2(R, addr) \
    asm volatile("ldmatrix.sync.aligned.m8n8.x2.shared.b16 {%0,%1}, [%2];" \
        : "=r"((R)[0]), "=r"((R)[1]) : "r"(addr))

__device__ __forceinline__ void mma_f16(float* d, const uint32_t* a, const uint32_t* b) {
    asm volatile(
        "mma.sync.aligned.m16n8k16.row.col.f32.f16.f16.f32 "
        "{%0,%1,%2,%3}, {%4,%5,%6,%7}, {%8,%9}, {%0,%1,%2,%3};"
        : "+f"(d[0]), "+f"(d[1]), "+f"(d[2]), "+f"(d[3])
        : "r"(a[0]), "r"(a[1]), "r"(a[2]), "r"(a[3]), "r"(b[0]), "r"(b[1]));
}

__device__ __forceinline__ uint32_t pack_h2(__half x, __half y) {
    return ((uint32_t)*(uint16_t*)&y << 16) | *(uint16_t*)&x;
}

__device__ __forceinline__ void red_add_v4(float* p, float4 v) {
    asm volatile("red.global.add.v4.f32 [%0], {%1, %2, %3, %4};"
                 :: "l"(p), "f"(v.x), "f"(v.y), "f"(v.z), "f"(v.w) : "memory");
}

// ================= fused setup kernel =================
// [0,T1)        : stage W fp16
// [T1,T1+800)   : BN fold
// [.., +NN*80)  : zero pads: bufA/B/C cols [400,416); P0/P1 group 25
#define T1 (NMATS * DD * WPITCH)
#define SETUP_TOTAL (T1 + 800 + NN * 80)

__global__ void setup_kernel(
    const float* __restrict__ w0, const float* __restrict__ w1,
    const float* __restrict__ w2, const float* __restrict__ w3,
    const float* __restrict__ w4, const float* __restrict__ w5,
    const float* __restrict__ w6,
    const float* __restrict__ b1a, const float* __restrict__ g1,
    const float* __restrict__ bb1, const float* __restrict__ m1,
    const float* __restrict__ v1,
    const float* __restrict__ b1b, const float* __restrict__ g2,
    const float* __restrict__ bb2, const float* __restrict__ m2,
    const float* __restrict__ v2) {
    int idx = blockIdx.x * blockDim.x + threadIdx.x;
    if (idx < T1) {
        const int per_mat = DD * WPITCH;
        int m = idx / per_mat;
        int r = idx - m * per_mat;
        int n = r / WPITCH;
        int k = r - n * WPITCH;
        int Km = (m == 0) ? FIN : DD;
        const float* W;
        switch (m) {
            case 0: W = w0; break; case 1: W = w1; break; case 2: W = w2; break;
            case 3: W = w3; break; case 4: W = w4; break; case 5: W = w5; break;
            default: W = w6; break;
        }
        float val = (k < Km) ? W[(size_t)k * DD + n] : 0.0f;
        g_Wh[idx] = __float2half(val);
    } else if (idx < T1 + 800) {
        int j = idx - T1;
        if (j < DD) {
            float a = g1[j] * rsqrtf(v1[j] + BN_EPS);
            g_alpha1[j] = a;
            g_beta1[j]  = (b1a[j] - m1[j]) * a + bb1[j];
        } else {
            int c = j - DD;
            float a = g2[c] * rsqrtf(v2[c] + BN_EPS);
            g_alpha2[c] = a;
            g_beta2[c]  = (b1b[c] - m2[c]) * a + bb2[c];
        }
    } else if (idx < SETUP_TOTAL) {
        int j = idx - T1 - 800;
        int row = j / 80;
        int t = j - row * 80;
        if (t < 16)      g_bufA[(size_t)row * PITCH + DD + t] = 0.0f;
        else if (t < 32) g_bufB[(size_t)row * PITCH + DD + (t - 16)] = 0.0f;
        else if (t < 48) g_bufC[(size_t)row * PITCH + DD + (t - 32)] = 0.0f;
        else if (t < 64) g_P0[(size_t)row * (PKPITCH / 4) + 400 + (t - 48)] = 0u;
        else             g_P1[(size_t)row * (PKPITCH / 4) + 400 + (t - 64)] = 0u;
    }
}

// ================= layer-1 glue =================

__global__ void pad_scale_kernel(const float* __restrict__ x,
                                 const float* __restrict__ eps) {
    int idx = blockIdx.x * blockDim.x + threadIdx.x;
    if (idx >= NN * XPITCH) return;
    int row = idx / XPITCH;
    int col = idx - row * XPITCH;
    float v = (col < FIN) ? x[(size_t)row * FIN + col] : 0.0f;
    g_xpad[idx] = v;
    g_z1[idx]   = (1.0f + eps[0]) * v;
}

__global__ void scatter_add_x_kernel(const int* __restrict__ src,
                                     const int* __restrict__ dst) {
    int idx = blockIdx.x * blockDim.x + threadIdx.x;
    if (idx >= EE * (XPITCH / 4)) return;
    int e = idx / (XPITCH / 4);
    int q = idx - e * (XPITCH / 4);
    const float4 v = *(const float4*)(g_xpad + (size_t)src[e] * XPITCH + q * 4);
    red_add_v4(g_z1 + (size_t)dst[e] * XPITCH + q * 4, v);
}

__global__ void scatter_add4_kernel(const float* __restrict__ h,
                                    const int* __restrict__ src,
                                    const int* __restrict__ dst,
                                    float* __restrict__ z) {
    int idx = blockIdx.x * blockDim.x + threadIdx.x;
    if (idx >= EE * (DD / 4)) return;
    int e = idx / (DD / 4);
    int q = idx - e * (DD / 4);
    const float4 v = *(const float4*)(h + (size_t)src[e] * PITCH + q * 4);
    red_add_v4(z + (size_t)dst[e] * PITCH + q * 4, v);
}

// ================= HMMA GEMM =================
// ASRC 0: A fp32 (lda pitch) -> in-smem fp16 hi/lo split (R11 pipeline).
// ASRC 1: A packed hi/lo (PKPITCH bytes/row; per 16-k group: 32B hi | 32B lo)
//          -> cp.async + direct ldmatrix, no split, 3-stage, 1 barrier/kb.
// MODE 0: relu -> packed output OPk.  MODE 1: tanh -> fp32 Cf (+ Zinit).
// INVARIANT: input and outputs pairwise distinct buffers.
#define BM 64
#define BN 200
#define GTHREADS 320
// --- ASRC0 layout (R11) ---
#define AF_STAGE 9216
#define AF_BASE  0
#define PL_BASE  (3 * AF_STAGE)
#define PL_SLOT  10240
#define PL_HI(p) (PL_BASE + (p) * PL_SLOT)
#define B0_BASE  (PL_BASE + 2 * PL_SLOT)
#define B_STAGE  16000
#define GSMEM0   (B0_BASE + 3 * B_STAGE)      // 96128
// --- ASRC1 layout ---
#define APK_BYTES 9216                        // 64 rows * 144B
#define ST1_STAGE (APK_BYTES + B_STAGE)       // 25216
#define GSMEM1    (3 * ST1_STAGE)             // 75648

__device__ __forceinline__ void load_stage0(
    uint32_t sb, int st,
    const float* __restrict__ A, int lda,
    const __half* __restrict__ Wh,
    int m0, int n0, int kb, int tid) {
    int k0 = kb * 32;
    uint32_t af = sb + AF_BASE + st * AF_STAGE;
    uint32_t bb = sb + B0_BASE + st * B_STAGE;
#pragma unroll 1
    for (int id = tid; id < 1312; id += GTHREADS) {
        if (id < 512) {
            int row = id >> 3, ch = id & 7;
            int gr = m0 + row;
            bool valid = gr < NN;
            size_t goff = valid ? ((size_t)gr * lda + k0 + ch * 4) : 0;
            cp16(af + row * 144 + ch * 16, A + goff, valid);
        } else {
            int id2 = id - 512;
            int row = id2 >> 2, ch = id2 & 3;
            size_t goff = (size_t)(n0 + row) * WPITCH + k0 + ch * 8;
            cp16(bb + row * 80 + ch * 16, Wh + goff, true);
        }
    }
}

__device__ __forceinline__ void load_stage1(
    uint32_t sb, int st,
    const char* __restrict__ Apk,
    const __half* __restrict__ Wh,
    int m0, int n0, int kb, int tid) {
    int k0 = kb * 32;
    uint32_t ab = sb + st * ST1_STAGE;
    uint32_t bb = ab + APK_BYTES;
#pragma unroll 1
    for (int id = tid; id < 1312; id += GTHREADS) {
        if (id < 512) {
            int row = id >> 3, ch = id & 7;
            int gr = m0 + row;
            bool valid = gr < NN;
            size_t goff = valid ? ((size_t)gr * PKPITCH + kb * 128 + ch * 16) : 0;
            cp16(ab + row * 144 + ch * 16, Apk + goff, valid);
        } else {
            int id2 = id - 512;
            int row = id2 >> 2, ch = id2 & 3;
            size_t goff = (size_t)(n0 + row) * WPITCH + k0 + ch * 8;
            cp16(bb + row * 80 + ch * 16, Wh + goff, true);
        }
    }
}

// split AF stage st -> plane buffer p (ASRC0 only)
__device__ __forceinline__ void split_tile(char* smem, int st, int p, int tid) {
    if (tid < 256) {
        char* af = smem + AF_BASE + st * AF_STAGE;
        int row = tid >> 2, ch = tid & 3;
        const float4 v0 = *(const float4*)(af + row * 144 + ch * 32);
        const float4 v1 = *(const float4*)(af + row * 144 + ch * 32 + 16);
        float f[8] = {v0.x, v0.y, v0.z, v0.w, v1.x, v1.y, v1.z, v1.w};
        uint32_t hp[4], lp[4];
#pragma unroll
        for (int j = 0; j < 4; j++) {
            __half h0 = __float2half(f[2 * j]);
            __half h1 = __float2half(f[2 * j + 1]);
            __half l0 = __float2half(f[2 * j]     - __half2float(h0));
            __half l1 = __float2half(f[2 * j + 1] - __half2float(h1));
            hp[j] = pack_h2(h0, h1);
            lp[j] = pack_h2(l0, l1);
        }
        *(uint4*)(smem + PL_HI(p) + row * 80 + ch * 16) = make_uint4(hp[0], hp[1], hp[2], hp[3]);
        *(uint4*)(smem + PL_HI(p) + 5120 + row * 80 + ch * 16) = make_uint4(lp[0], lp[1], lp[2], lp[3]);
    }
}

template <int ASRC, int MODE>
__global__ __launch_bounds__(GTHREADS, 2) void gemm_hmma_kernel(
    const float* __restrict__ Af, int lda,
    const char* __restrict__ Apk,
    int kblks,
    const __half* __restrict__ Wh,
    const float* __restrict__ alpha, const float* __restrict__ beta,
    char* __restrict__ OPk,
    float* __restrict__ Cf,
    const float* __restrict__ epsn, float* __restrict__ Zinit) {
    extern __shared__ char smem[];
    uint32_t sb = smem_to_u32(smem);
    int tid  = threadIdx.x;
    int wid  = tid >> 5;
    int lane = tid & 31;
    int wm = wid / 5;            // 0..1
    int wn = wid - wm * 5;       // 0..4
    int m0 = blockIdx.x * BM;
    int n0 = blockIdx.y * BN;

    float acc[2][5][4];
#pragma unroll
    for (int i = 0; i < 2; i++)
#pragma unroll
        for (int j = 0; j < 5; j++)
#pragma unroll
            for (int k = 0; k < 4; k++) acc[i][j][k] = 0.0f;

    // prologue
    if (ASRC == 0) {
        load_stage0(sb, 0, Af, lda, Wh, m0, n0, 0, tid);
        CP_COMMIT();
        load_stage0(sb, 1, Af, lda, Wh, m0, n0, 1, tid);
        CP_COMMIT();
        CP_WAIT(1);
        __syncthreads();
        split_tile(smem, 0, 0, tid);
    } else {
        load_stage1(sb, 0, Apk, Wh, m0, n0, 0, tid);
        CP_COMMIT();
        load_stage1(sb, 1, Apk, Wh, m0, n0, 1, tid);
        CP_COMMIT();
    }

#pragma unroll 1
    for (int kb = 0; kb < kblks; kb++) {
        if (ASRC == 0) {
            CP_WAIT(0);
            __syncthreads();   // publish cp.async + split(kb); fence reuse
            if (kb + 2 < kblks) {
                load_stage0(sb, (kb + 2) % 3, Af, lda, Wh, m0, n0, kb + 2, tid);
                CP_COMMIT();
            }
            if (kb + 1 < kblks)
                split_tile(smem, (kb + 1) % 3, (kb + 1) & 1, tid);
        } else {
            if (kb + 1 < kblks) { CP_WAIT(1); } else { CP_WAIT(0); }
            __syncthreads();   // publish stage kb; fence stage (kb+2)%3 reuse
            if (kb + 2 < kblks) {
                load_stage1(sb, (kb + 2) % 3, Apk, Wh, m0, n0, kb + 2, tid);
                CP_COMMIT();
            }
        }

        // fragment addressing (compile-time selected)
        uint32_t aBase, bb;
        if (ASRC == 0) {
            aBase = sb + PL_HI(kb & 1);
            bb    = sb + B0_BASE + (kb % 3) * B_STAGE;
        } else {
            aBase = sb + (kb % 3) * ST1_STAGE;
            bb    = aBase + APK_BYTES;
        }
        const int aRowS = (ASRC == 0) ? 80 : 144;
        const int aKKS  = (ASRC == 0) ? 32 : 64;
        const int aLoO  = (ASRC == 0) ? 5120 : 32;

#pragma unroll
        for (int kk = 0; kk < 2; kk++) {
            uint32_t af[2][2][4];   // [plane][mtile][4]
#pragma unroll
            for (int mt = 0; mt < 2; mt++) {
                uint32_t row  = wm * 32 + mt * 16 + (lane & 15);
                uint32_t addr = aBase + row * aRowS + kk * aKKS + ((lane >> 4) << 4);
                LDSM4(af[0][mt], addr);
                LDSM4(af[1][mt], addr + aLoO);
            }
            uint32_t bfr[5][2];
            {
                int l8  = lane & 7;
                int grp = lane >> 3;           // 0..3
#pragma unroll
                for (int pr = 0; pr < 2; pr++) {
                    uint32_t rowB = wn * 40 + pr * 16 + (grp >> 1) * 8 + l8;
                    uint32_t addr = bb + rowB * 80 + kk * 32 + ((grp & 1) << 4);
                    LDSM4P(bfr[2 * pr][0], bfr[2 * pr][1],
                           bfr[2 * pr + 1][0], bfr[2 * pr + 1][1], addr);
                }
                uint32_t rowB = wn * 40 + 32 + l8;
                uint32_t addr = bb + rowB * 80 + kk * 32 + (((lane >> 3) & 1) << 4);
                LDSM2(bfr[4], addr);
            }
#pragma unroll
            for (int mt = 0; mt < 2; mt++)
#pragma unroll
                for (int nt = 0; nt < 5; nt++) {
                    mma_f16(acc[mt][nt], af[0][mt], bfr[nt]);  // Ah * W
                    mma_f16(acc[mt][nt], af[1][mt], bfr[nt]);  // Al * W
                }
        }
    }

    // ---------------- epilogue ----------------
    float sc = (MODE == 1 && Zinit) ? (1.0f + epsn[0]) : 0.0f;
#pragma unroll
    for (int mt = 0; mt < 2; mt++) {
#pragma unroll
        for (int nt = 0; nt < 5; nt++) {
            int c  = n0 + wn * 40 + nt * 8 + (lane & 3) * 2;
            int r0 = m0 + wm * 32 + mt * 16 + (lane >> 2);
            float a0 = alpha ? alpha[c]     : 1.0f;
            float a1 = alpha ? alpha[c + 1] : 1.0f;
            float b0 = beta[c], b1 = beta[c + 1];
            float v00 = acc[mt][nt][0] * a0 + b0;
            float v01 = acc[mt][nt][1] * a1 + b1;
            float v10 = acc[mt][nt][2] * a0 + b0;
            float v11 = acc[mt][nt][3] * a1 + b1;
            if (MODE == 0) {
                v00 = fmaxf(v00, 0.f); v01 = fmaxf(v01, 0.f);
                v10 = fmaxf(v10, 0.f); v11 = fmaxf(v11, 0.f);
                size_t goff = (size_t)(c >> 4) * 64 + (size_t)(c & 15) * 2;
                if (r0 < NN) {
                    __half h0 = __float2half(v00);
                    __half h1 = __float2half(v01);
                    char* p = OPk + (size_t)r0 * PKPITCH + goff;
                    *(uint32_t*)p = pack_h2(h0, h1);
                    *(uint32_t*)(p + 32) = pack_h2(__float2half(v00 - __half2float(h0)),
                                                   __float2half(v01 - __half2float(h1)));
                }
                if (r0 + 8 < NN) {
                    __half h0 = __float2half(v10);
                    __half h1 = __float2half(v11);
                    char* p = OPk + (size_t)(r0 + 8) * PKPITCH + goff;
                    *(uint32_t*)p = pack_h2(h0, h1);
                    *(uint32_t*)(p + 32) = pack_h2(__float2half(v10 - __half2float(h0)),
                                                   __float2half(v11 - __half2float(h1)));
                }
            } else {
                float t00 = tanhf(v00), t01 = tanhf(v01);
                float t10 = tanhf(v10), t11 = tanhf(v11);
                if (r0 < NN) {
                    *(float2*)(Cf + (size_t)r0 * PITCH + c) = make_float2(t00, t01);
                    if (Zinit)
                        *(float2*)(Zinit + (size_t)r0 * PITCH + c) =
                            make_float2(sc * t00, sc * t01);
                }
                if (r0 + 8 < NN) {
                    *(float2*)(Cf + (size_t)(r0 + 8) * PITCH + c) = make_float2(t10, t11);
                    if (Zinit)
                        *(float2*)(Zinit + (size_t)(r0 + 8) * PITCH + c) =
                            make_float2(sc * t10, sc * t11);
                }
            }
        }
    }
}

// ================= pooling + final projection (atomic-free) =================

__device__ __forceinline__ int lower_bound_batch(const int* __restrict__ b, int val) {
    int lo = 0, hi = NN;
    while (lo < hi) {
        int mid = (lo + hi) >> 1;
        if (b[mid] < val) lo = mid + 1; else hi = mid;
    }
    return lo;
}

__global__ __launch_bounds__(256) void pool_out_kernel(
    const float* __restrict__ h, const int* __restrict__ batch,
    const float* __restrict__ w, const float* __restrict__ b,
    float* __restrict__ out) {
    int g   = blockIdx.x;
    int tid = threadIdx.x;
    int lo = lower_bound_batch(batch, g);
    int hi = lower_bound_batch(batch, g + 1);
    float invc = 1.0f / fmaxf((float)(hi - lo), 1.0f);
    float part = 0.0f;
    for (int f = tid; f < DD; f += 256) {
        float mx = -INFINITY, sm = 0.0f;
        for (int node = lo; node < hi; node++) {
            float v = h[(size_t)node * PITCH + f];
            mx = fmaxf(mx, v);
            sm += v;
        }
        if (hi == lo) mx = 0.0f;
        part += mx * w[f] + sm * invc * w[DD + f];
    }
#pragma unroll
    for (int o = 16; o > 0; o >>= 1) part += __shfl_down_sync(0xffffffffu, part, o);
    __shared__ float sh[8];
    if ((tid & 31) == 0) sh[tid >> 5] = part;
    __syncthreads();
    if (tid == 0) {
        float t = 0.0f;
#pragma unroll
        for (int i = 0; i < 8; i++) t += sh[i];
        out[g] = t + b[0];
    }
}

// ================= host orchestration =================

static inline int ceil_div(int a, int b) { return (a + b - 1) / b; }

extern "C" void kernel_launch(void* const* d_in, const int* in_sizes, int n_in,
                              void* d_out, int out_size) {
    const float* x     = (const float*)d_in[0];
    const int*   ei    = (const int*)d_in[1];
    const int*   src   = ei;
    const int*   dst   = ei + EE;
    const int*   batch = (const int*)d_in[2];
    int base = (in_sizes[3] == 1) ? 4 : 3;

    const float* mlp1_w1   = (const float*)d_in[base + 0];
    const float* mlp1_b1   = (const float*)d_in[base + 1];
    const float* mlp1_bn_g = (const float*)d_in[base + 2];
    const float* mlp1_bn_b = (const float*)d_in[base + 3];
    const float* mlp1_bn_m = (const float*)d_in[base + 4];
    const float* mlp1_bn_v = (const float*)d_in[base + 5];
    const float* mlp1_w2   = (const float*)d_in[base + 6];
    const float* mlp1_b2   = (const float*)d_in[base + 7];
    const float* mlp2_w1   = (const float*)d_in[base + 8];
    const float* mlp2_b1   = (const float*)d_in[base + 9];
    const float* mlp2_bn_g = (const float*)d_in[base + 10];
    const float* mlp2_bn_b = (const float*)d_in[base + 11];
    const float* mlp2_bn_m = (const float*)d_in[base + 12];
    const float* mlp2_bn_v = (const float*)d_in[base + 13];
    const float* mlp2_w2   = (const float*)d_in[base + 14];
    const float* mlp2_b2   = (const float*)d_in[base + 15];
    const float* out1_w    = (const float*)d_in[base + 16];
    const float* out1_b    = (const float*)d_in[base + 17];
    const float* out2_w    = (const float*)d_in[base + 18];
    const float* out2_b    = (const float*)d_in[base + 19];
    const float* out3_w    = (const float*)d_in[base + 20];
    const float* out3_b    = (const float*)d_in[base + 21];
    const float* out_w     = (const float*)d_in[base + 22];
    const float* out_b     = (const float*)d_in[base + 23];
    const float* eps1      = (const float*)d_in[base + 24];
    const float* eps2      = (const float*)d_in[base + 25];
    const float* eps3      = (const float*)d_in[base + 26];

    float* out = (float*)d_out;

    float *bufA, *bufB, *bufC, *z1, *alpha1, *beta1, *alpha2, *beta2;
    __half* wh;
    char *p0, *p1;
    cudaGetSymbolAddress((void**)&bufA, g_bufA);
    cudaGetSymbolAddress((void**)&bufB, g_bufB);
    cudaGetSymbolAddress((void**)&bufC, g_bufC);
    cudaGetSymbolAddress((void**)&z1,   g_z1);
    cudaGetSymbolAddress((void**)&alpha1, g_alpha1);
    cudaGetSymbolAddress((void**)&beta1,  g_beta1);
    cudaGetSymbolAddress((void**)&alpha2, g_alpha2);
    cudaGetSymbolAddress((void**)&beta2,  g_beta2);
    cudaGetSymbolAddress((void**)&wh, g_Wh);
    cudaGetSymbolAddress((void**)&p0, g_P0);
    cudaGetSymbolAddress((void**)&p1, g_P1);

    cudaFuncSetAttribute(gemm_hmma_kernel<0, 0>,
                         cudaFuncAttributeMaxDynamicSharedMemorySize, GSMEM0);
    cudaFuncSetAttribute(gemm_hmma_kernel<1, 0>,
                         cudaFuncAttributeMaxDynamicSharedMemorySize, GSMEM1);
    cudaFuncSetAttribute(gemm_hmma_kernel<1, 1>,
                         cudaFuncAttributeMaxDynamicSharedMemorySize, GSMEM1);

    dim3 ggrid(ceil_div(NN, BM), 2);   // (782, 2) = 1564 CTAs
    size_t wmat = (size_t)DD * WPITCH;

    // 1: fused setup
    setup_kernel<<<ceil_div(SETUP_TOTAL, 256), 256>>>(
        mlp1_w1, mlp1_w2, mlp2_w1, mlp2_w2, out1_w, out2_w, out3_w,
        mlp1_b1, mlp1_bn_g, mlp1_bn_b, mlp1_bn_m, mlp1_bn_v,
        mlp2_b1, mlp2_bn_g, mlp2_bn_b, mlp2_bn_m, mlp2_bn_v);

    // ---------- layer 1 ----------
    pad_scale_kernel<<<ceil_div(NN * XPITCH, 256), 256>>>(x, eps1);
    scatter_add_x_kernel<<<ceil_div(EE * (XPITCH / 4), 256), 256>>>(src, dst);
    gemm_hmma_kernel<0, 0><<<ggrid, GTHREADS, GSMEM0>>>(
        z1, XPITCH, nullptr, 3, wh + 0 * wmat,
        alpha1, beta1, p0, nullptr, nullptr, nullptr);
    gemm_hmma_kernel<1, 0><<<ggrid, GTHREADS, GSMEM1>>>(
        nullptr, 0, p0, 13, wh + 1 * wmat,
        nullptr, mlp1_b2, p1, nullptr, nullptr, nullptr);
    // tanh: h1 -> bufA, (1+eps2)*h1 -> bufC
    gemm_hmma_kernel<1, 1><<<ggrid, GTHREADS, GSMEM1>>>(
        nullptr, 0, p1, 13, wh + 4 * wmat,
        nullptr, out1_b, nullptr, bufA, eps2, bufC);
    // ---------- layer 2 ----------
    scatter_add4_kernel<<<ceil_div(EE * (DD / 4), 256), 256>>>(bufA, src, dst, bufC);
    gemm_hmma_kernel<0, 0><<<ggrid, GTHREADS, GSMEM0>>>(
        bufC, PITCH, nullptr, 13, wh + 2 * wmat,
        alpha2, beta2, p0, nullptr, nullptr, nullptr);
    gemm_hmma_kernel<1, 0><<<ggrid, GTHREADS, GSMEM1>>>(
        nullptr, 0, p0, 13, wh + 3 * wmat,
        nullptr, mlp2_b2, p1, nullptr, nullptr, nullptr);
    // tanh: h2 -> bufB, (1+eps3)*h2 -> bufC
    gemm_hmma_kernel<1, 1><<<ggrid, GTHREADS, GSMEM1>>>(
        nullptr, 0, p1, 13, wh + 5 * wmat,
        nullptr, out2_b, nullptr, bufB, eps3, bufC);
    // ---------- layer 3 ----------
    scatter_add4_kernel<<<ceil_div(EE * (DD / 4), 256), 256>>>(bufB, src, dst, bufC);
    gemm_hmma_kernel<0, 0><<<ggrid, GTHREADS, GSMEM0>>>(
        bufC, PITCH, nullptr, 13, wh + 2 * wmat,
        alpha2, beta2, p0, nullptr, nullptr, nullptr);
    gemm_hmma_kernel<1, 0><<<ggrid, GTHREADS, GSMEM1>>>(
        nullptr, 0, p0, 13, wh + 3 * wmat,
        nullptr, mlp2_b2, p1, nullptr, nullptr, nullptr);
    gemm_hmma_kernel<1, 1><<<ggrid, GTHREADS, GSMEM1>>>(
        nullptr, 0, p1, 13, wh + 6 * wmat,
        nullptr, out3_b, nullptr, bufA, nullptr, nullptr);
    // ---------- pooling + output ----------
    pool_out_kernel<<<GG, 256>>>(bufA, batch, out_w, out_b, out);
    (void)n_in; (void)out_size;
}

// round 13
// speedup vs baseline: 1.0152x; 1.0152x over previous
#include <cuda_runtime.h>
#include <cuda_fp16.h>
#include <cstdint>
#include <math.h>

// ================= problem constants =================
#define NN    50000
#define EE    400000
#define GG    256
#define FIN   79
#define DD    400
#define BN_EPS 1e-5f

#define NMATS  7
#define WPITCH 416            // staged weight K pitch (halfs)
#define PITCH  416            // fp32 activation pitch (13 * 32)
#define XPITCH 96             // layer-1 fp32 pitch (3 * 32)

// ================= scratch (device globals; zero-initialized) ============
__device__ float g_bufA[(size_t)NN * PITCH];
__device__ float g_bufB[(size_t)NN * PITCH];
__device__ float g_bufC[(size_t)NN * PITCH];
__device__ float g_xpad[(size_t)NN * XPITCH];
__device__ float g_z1[(size_t)NN * XPITCH];
__device__ __align__(16) __half g_Wh[(size_t)NMATS * DD * WPITCH];
__device__ float g_alpha1[DD], g_beta1[DD], g_alpha2[DD], g_beta2[DD];

// ================= helpers =================
__device__ __forceinline__ uint32_t smem_to_u32(const void* p) {
    uint32_t a;
    asm("{ .reg .u64 t; cvta.to.shared.u64 t, %1; cvt.u32.u64 %0, t; }"
        : "=r"(a) : "l"(p));
    return a;
}

__device__ __forceinline__ void cp16(uint32_t saddr, const void* gptr, bool valid) {
    int sz = valid ? 16 : 0;
    asm volatile("cp.async.cg.shared.global [%0], [%1], 16, %2;"
                 :: "r"(saddr), "l"(gptr), "r"(sz));
}
#define CP_COMMIT() asm volatile("cp.async.commit_group;")
#define CP_WAIT(n)  asm volatile("cp.async.wait_group %0;" :: "n"(n))

#define LDSM4(R, addr) \
    asm volatile("ldmatrix.sync.aligned.m8n8.x4.shared.b16 {%0,%1,%2,%3}, [%4];" \
        : "=r"((R)[0]), "=r"((R)[1]), "=r"((R)[2]), "=r"((R)[3]) : "r"(addr))

#define LDSM4P(r0, r1, r2, r3, addr) \
    asm volatile("ldmatrix.sync.aligned.m8n8.x4.shared.b16 {%0,%1,%2,%3}, [%4];" \
        : "=r"(r0), "=r"(r1), "=r"(r2), "=r"(r3) : "r"(addr))

#define LDSM2(R, addr) \
    asm volatile("ldmatrix.sync.aligned.m8n8.x2.shared.b16 {%0,%1}, [%2];" \
        : "=r"((R)[0]), "=r"((R)[1]) : "r"(addr))

__device__ __forceinline__ void mma_f16(float* d, const uint32_t* a, const uint32_t* b) {
    asm volatile(
        "mma.sync.aligned.m16n8k16.row.col.f32.f16.f16.f32 "
        "{%0,%1,%2,%3}, {%4,%5,%6,%7}, {%8,%9}, {%0,%1,%2,%3};"
        : "+f"(d[0]), "+f"(d[1]), "+f"(d[2]), "+f"(d[3])
        : "r"(a[0]), "r"(a[1]), "r"(a[2]), "r"(a[3]), "r"(b[0]), "r"(b[1]));
}

__device__ __forceinline__ uint32_t pack_h2(__half x, __half y) {
    return ((uint32_t)*(uint16_t*)&y << 16) | *(uint16_t*)&x;
}

__device__ __forceinline__ void red_add_v4(float* p, float4 v) {
    asm volatile("red.global.add.v4.f32 [%0], {%1, %2, %3, %4};"
                 :: "l"(p), "f"(v.x), "f"(v.y), "f"(v.z), "f"(v.w) : "memory");
}

// fast tanh: exp2-based, ~1e-6 relative accuracy, saturates correctly.
__device__ __forceinline__ float fast_tanh(float x) {
    float a = fabsf(x);
    float t = __expf(-2.0f * a);          // underflows to 0 for large a
    float r = __fdividef(1.0f - t, 1.0f + t);
    return copysignf(r, x);
}

// ================= fused setup kernel =================
#define T1 (NMATS * DD * WPITCH)
#define SETUP_TOTAL (T1 + 800 + NN * 48)

__global__ void setup_kernel(
    const float* __restrict__ w0, const float* __restrict__ w1,
    const float* __restrict__ w2, const float* __restrict__ w3,
    const float* __restrict__ w4, const float* __restrict__ w5,
    const float* __restrict__ w6,
    const float* __restrict__ b1a, const float* __restrict__ g1,
    const float* __restrict__ bb1, const float* __restrict__ m1,
    const float* __restrict__ v1,
    const float* __restrict__ b1b, const float* __restrict__ g2,
    const float* __restrict__ bb2, const float* __restrict__ m2,
    const float* __restrict__ v2) {
    int idx = blockIdx.x * blockDim.x + threadIdx.x;
    if (idx < T1) {
        const int per_mat = DD * WPITCH;
        int m = idx / per_mat;
        int r = idx - m * per_mat;
        int n = r / WPITCH;
        int k = r - n * WPITCH;
        int Km = (m == 0) ? FIN : DD;
        const float* W;
        switch (m) {
            case 0: W = w0; break; case 1: W = w1; break; case 2: W = w2; break;
            case 3: W = w3; break; case 4: W = w4; break; case 5: W = w5; break;
            default: W = w6; break;
        }
        float val = (k < Km) ? W[(size_t)k * DD + n] : 0.0f;
        g_Wh[idx] = __float2half(val);
    } else if (idx < T1 + 800) {
        int j = idx - T1;
        if (j < DD) {
            float a = g1[j] * rsqrtf(v1[j] + BN_EPS);
            g_alpha1[j] = a;
            g_beta1[j]  = (b1a[j] - m1[j]) * a + bb1[j];
        } else {
            int c = j - DD;
            float a = g2[c] * rsqrtf(v2[c] + BN_EPS);
            g_alpha2[c] = a;
            g_beta2[c]  = (b1b[c] - m2[c]) * a + bb2[c];
        }
    } else if (idx < SETUP_TOTAL) {
        int j = idx - T1 - 800;
        int row = j / 48;
        int t = j - row * 48;
        if (t < 16)      g_bufA[(size_t)row * PITCH + DD + t] = 0.0f;
        else if (t < 32) g_bufB[(size_t)row * PITCH + DD + (t - 16)] = 0.0f;
        else             g_bufC[(size_t)row * PITCH + DD + (t - 32)] = 0.0f;
    }
}

// ================= layer-1 glue =================

__global__ void pad_scale_kernel(const float* __restrict__ x,
                                 const float* __restrict__ eps) {
    int idx = blockIdx.x * blockDim.x + threadIdx.x;
    if (idx >= NN * XPITCH) return;
    int row = idx / XPITCH;
    int col = idx - row * XPITCH;
    float v = (col < FIN) ? x[(size_t)row * FIN + col] : 0.0f;
    g_xpad[idx] = v;
    g_z1[idx]   = (1.0f + eps[0]) * v;
}

__global__ void scatter_add_x_kernel(const int* __restrict__ src,
                                     const int* __restrict__ dst) {
    int idx = blockIdx.x * blockDim.x + threadIdx.x;
    if (idx >= EE * (XPITCH / 4)) return;
    int e = idx / (XPITCH / 4);
    int q = idx - e * (XPITCH / 4);
    const float4 v = *(const float4*)(g_xpad + (size_t)src[e] * XPITCH + q * 4);
    red_add_v4(g_z1 + (size_t)dst[e] * XPITCH + q * 4, v);
}

__global__ void scatter_add4_kernel(const float* __restrict__ h,
                                    const int* __restrict__ src,
                                    const int* __restrict__ dst,
                                    float* __restrict__ z) {
    int idx = blockIdx.x * blockDim.x + threadIdx.x;
    if (idx >= EE * (DD / 4)) return;
    int e = idx / (DD / 4);
    int q = idx - e * (DD / 4);
    const float4 v = *(const float4*)(h + (size_t)src[e] * PITCH + q * 4);
    red_add_v4(z + (size_t)dst[e] * PITCH + q * 4, v);
}

// ================= HMMA GEMM: fp32 A, in-smem fp16 hi/lo split =============
// BM=64, 320 threads, 2 CTAs/SM. ONE barrier per k-block: split of the next
// k-block's planes is overlapped with the current k-block's MMAs.
// AF/B: 3 cp.async stages. Planes: independent 2-slot double buffer.
// MODE 0: relu -> fp32 Cf.  MODE 1: tanh -> fp32 Cf (+ (1+eps)*tanh -> Zinit)
// INVARIANT: A, Cf, Zinit pairwise distinct.
#define BM 64
#define BN 200
#define GTHREADS 320
#define AF_STAGE 9216                  // fp32 A tile: 64 rows * 144B
#define AF_BASE  0                     // 3 stages: [0, 27648)
#define PL_BASE  (3 * AF_STAGE)        // 2 plane buffers (hi 5120 + lo 5120 each)
#define PL_SLOT  10240
#define PL_HI(p) (PL_BASE + (p) * PL_SLOT)
#define B_BASE   (PL_BASE + 2 * PL_SLOT)   // 48128
#define B_STAGE  16000
#define GSMEM    (B_BASE + 3 * B_STAGE)    // 96128 (2 CTAs = 192256 < 228K)

__device__ __forceinline__ void load_stage(
    uint32_t sb, int st,
    const float* __restrict__ A, int lda,
    const __half* __restrict__ Wh,
    int m0, int n0, int kb, int tid) {
    int k0 = kb * 32;
    uint32_t af = sb + AF_BASE + st * AF_STAGE;
    uint32_t bb = sb + B_BASE + st * B_STAGE;
#pragma unroll 1
    for (int id = tid; id < 1312; id += GTHREADS) {
        if (id < 512) {
            int row = id >> 3, ch = id & 7;
            int gr = m0 + row;
            bool valid = gr < NN;
            size_t goff = valid ? ((size_t)gr * lda + k0 + ch * 4) : 0;
            cp16(af + row * 144 + ch * 16, A + goff, valid);
        } else {
            int id2 = id - 512;
            int row = id2 >> 2, ch = id2 & 3;
            size_t goff = (size_t)(n0 + row) * WPITCH + k0 + ch * 8;
            cp16(bb + row * 80 + ch * 16, Wh + goff, true);
        }
    }
}

// split AF stage st -> plane buffer p
__device__ __forceinline__ void split_tile(char* smem, int st, int p, int tid) {
    if (tid < 256) {
        char* af = smem + AF_BASE + st * AF_STAGE;
        int row = tid >> 2, ch = tid & 3;
        const float4 v0 = *(const float4*)(af + row * 144 + ch * 32);
        const float4 v1 = *(const float4*)(af + row * 144 + ch * 32 + 16);
        float f[8] = {v0.x, v0.y, v0.z, v0.w, v1.x, v1.y, v1.z, v1.w};
        uint32_t hp[4], lp[4];
#pragma unroll
        for (int j = 0; j < 4; j++) {
            __half h0 = __float2half(f[2 * j]);
            __half h1 = __float2half(f[2 * j + 1]);
            __half l0 = __float2half(f[2 * j]     - __half2float(h0));
            __half l1 = __float2half(f[2 * j + 1] - __half2float(h1));
            hp[j] = pack_h2(h0, h1);
            lp[j] = pack_h2(l0, l1);
        }
        *(uint4*)(smem + PL_HI(p) + row * 80 + ch * 16) = make_uint4(hp[0], hp[1], hp[2], hp[3]);
        *(uint4*)(smem + PL_HI(p) + 5120 + row * 80 + ch * 16) = make_uint4(lp[0], lp[1], lp[2], lp[3]);
    }
}

template <int MODE>
__global__ __launch_bounds__(GTHREADS, 2) void gemm_hmma_kernel(
    const float* __restrict__ A, int lda, int kblks,
    const __half* __restrict__ Wh,
    const float* __restrict__ alpha, const float* __restrict__ beta,
    float* __restrict__ Cf,
    const float* __restrict__ epsn, float* __restrict__ Zinit) {
    extern __shared__ char smem[];
    uint32_t sb = smem_to_u32(smem);
    int tid  = threadIdx.x;
    int wid  = tid >> 5;
    int lane = tid & 31;
    int wm = wid / 5;            // 0..1
    int wn = wid - wm * 5;       // 0..4
    int m0 = blockIdx.x * BM;
    int n0 = blockIdx.y * BN;

    float acc[2][5][4];
#pragma unroll
    for (int i = 0; i < 2; i++)
#pragma unroll
        for (int j = 0; j < 5; j++)
#pragma unroll
            for (int k = 0; k < 4; k++) acc[i][j][k] = 0.0f;

    // prologue: load stages 0,1; split stage 0 into plane 0.
    load_stage(sb, 0, A, lda, Wh, m0, n0, 0, tid);
    CP_COMMIT();
    load_stage(sb, 1, A, lda, Wh, m0, n0, 1, tid);
    CP_COMMIT();
    CP_WAIT(1);
    __syncthreads();                    // publish AF0/B0
    split_tile(smem, 0, 0, tid);

#pragma unroll 1
    for (int kb = 0; kb < kblks; kb++) {
        CP_WAIT(0);        // group kb+1 complete (only outstanding group)
        __syncthreads();   // publish cp.async data + split(kb); fence reuse
        if (kb + 2 < kblks) {
            load_stage(sb, (kb + 2) % 3, A, lda, Wh, m0, n0, kb + 2, tid);
            CP_COMMIT();
        }
        if (kb + 1 < kblks)
            split_tile(smem, (kb + 1) % 3, (kb + 1) & 1, tid);

        uint32_t ph = sb + PL_HI(kb & 1);
        uint32_t bb = sb + B_BASE + (kb % 3) * B_STAGE;
#pragma unroll
        for (int kk = 0; kk < 2; kk++) {
            uint32_t af[2][2][4];   // [plane][mtile][4]
#pragma unroll
            for (int mt = 0; mt < 2; mt++) {
                uint32_t row  = wm * 32 + mt * 16 + (lane & 15);
                uint32_t addr = ph + row * 80 + kk * 32 + ((lane >> 4) << 4);
                LDSM4(af[0][mt], addr);
                LDSM4(af[1][mt], addr + 5120);   // lo plane
            }
            uint32_t bfr[5][2];
            {
                int l8  = lane & 7;
                int grp = lane >> 3;           // 0..3
#pragma unroll
                for (int pr = 0; pr < 2; pr++) {
                    uint32_t rowB = wn * 40 + pr * 16 + (grp >> 1) * 8 + l8;
                    uint32_t addr = bb + rowB * 80 + kk * 32 + ((grp & 1) << 4);
                    LDSM4P(bfr[2 * pr][0], bfr[2 * pr][1],
                           bfr[2 * pr + 1][0], bfr[2 * pr + 1][1], addr);
                }
                uint32_t rowB = wn * 40 + 32 + l8;
                uint32_t addr = bb + rowB * 80 + kk * 32 + (((lane >> 3) & 1) << 4);
                LDSM2(bfr[4], addr);
            }
#pragma unroll
            for (int mt = 0; mt < 2; mt++)
#pragma unroll
                for (int nt = 0; nt < 5; nt++) {
                    mma_f16(acc[mt][nt], af[0][mt], bfr[nt]);  // Ah * W
                    mma_f16(acc[mt][nt], af[1][mt], bfr[nt]);  // Al * W
                }
        }
    }

    // ---------------- epilogue ----------------
    float sc = (MODE == 1 && Zinit) ? (1.0f + epsn[0]) : 0.0f;
#pragma unroll
    for (int mt = 0; mt < 2; mt++) {
#pragma unroll
        for (int nt = 0; nt < 5; nt++) {
            int c  = n0 + wn * 40 + nt * 8 + (lane & 3) * 2;
            int r0 = m0 + wm * 32 + mt * 16 + (lane >> 2);
            float a0 = alpha ? alpha[c]     : 1.0f;
            float a1 = alpha ? alpha[c + 1] : 1.0f;
            float b0 = beta[c], b1 = beta[c + 1];
            float v00 = acc[mt][nt][0] * a0 + b0;
            float v01 = acc[mt][nt][1] * a1 + b1;
            float v10 = acc[mt][nt][2] * a0 + b0;
            float v11 = acc[mt][nt][3] * a1 + b1;
            if (MODE == 0) {
                if (r0 < NN)
                    *(float2*)(Cf + (size_t)r0 * PITCH + c) =
                        make_float2(fmaxf(v00, 0.f), fmaxf(v01, 0.f));
                if (r0 + 8 < NN)
                    *(float2*)(Cf + (size_t)(r0 + 8) * PITCH + c) =
                        make_float2(fmaxf(v10, 0.f), fmaxf(v11, 0.f));
            } else {
                float t00 = fast_tanh(v00), t01 = fast_tanh(v01);
                float t10 = fast_tanh(v10), t11 = fast_tanh(v11);
                if (r0 < NN) {
                    *(float2*)(Cf + (size_t)r0 * PITCH + c) = make_float2(t00, t01);
                    if (Zinit)
                        *(float2*)(Zinit + (size_t)r0 * PITCH + c) =
                            make_float2(sc * t00, sc * t01);
                }
                if (r0 + 8 < NN) {
                    *(float2*)(Cf + (size_t)(r0 + 8) * PITCH + c) = make_float2(t10, t11);
                    if (Zinit)
                        *(float2*)(Zinit + (size_t)(r0 + 8) * PITCH + c) =
                            make_float2(sc * t10, sc * t11);
                }
            }
        }
    }
}

// ================= pooling + final projection (atomic-free) =================

__device__ __forceinline__ int lower_bound_batch(const int* __restrict__ b, int val) {
    int lo = 0, hi = NN;
    while (lo < hi) {
        int mid = (lo + hi) >> 1;
        if (b[mid] < val) lo = mid + 1; else hi = mid;
    }
    return lo;
}

__global__ __launch_bounds__(256) void pool_out_kernel(
    const float* __restrict__ h, const int* __restrict__ batch,
    const float* __restrict__ w, const float* __restrict__ b,
    float* __restrict__ out) {
    int g   = blockIdx.x;
    int tid = threadIdx.x;
    int lo = lower_bound_batch(batch, g);
    int hi = lower_bound_batch(batch, g + 1);
    float invc = 1.0f / fmaxf((float)(hi - lo), 1.0f);
    float part = 0.0f;
    for (int f = tid; f < DD; f += 256) {
        float mx = -INFINITY, sm = 0.0f;
        for (int node = lo; node < hi; node++) {
            float v = h[(size_t)node * PITCH + f];
            mx = fmaxf(mx, v);
            sm += v;
        }
        if (hi == lo) mx = 0.0f;
        part += mx * w[f] + sm * invc * w[DD + f];
    }
#pragma unroll
    for (int o = 16; o > 0; o >>= 1) part += __shfl_down_sync(0xffffffffu, part, o);
    __shared__ float sh[8];
    if ((tid & 31) == 0) sh[tid >> 5] = part;
    __syncthreads();
    if (tid == 0) {
        float t = 0.0f;
#pragma unroll
        for (int i = 0; i < 8; i++) t += sh[i];
        out[g] = t + b[0];
    }
}

// ================= host orchestration =================

static inline int ceil_div(int a, int b) { return (a + b - 1) / b; }

extern "C" void kernel_launch(void* const* d_in, const int* in_sizes, int n_in,
                              void* d_out, int out_size) {
    const float* x     = (const float*)d_in[0];
    const int*   ei    = (const int*)d_in[1];
    const int*   src   = ei;
    const int*   dst   = ei + EE;
    const int*   batch = (const int*)d_in[2];
    int base = (in_sizes[3] == 1) ? 4 : 3;

    const float* mlp1_w1   = (const float*)d_in[base + 0];
    const float* mlp1_b1   = (const float*)d_in[base + 1];
    const float* mlp1_bn_g = (const float*)d_in[base + 2];
    const float* mlp1_bn_b = (const float*)d_in[base + 3];
    const float* mlp1_bn_m = (const float*)d_in[base + 4];
    const float* mlp1_bn_v = (const float*)d_in[base + 5];
    const float* mlp1_w2   = (const float*)d_in[base + 6];
    const float* mlp1_b2   = (const float*)d_in[base + 7];
    const float* mlp2_w1   = (const float*)d_in[base + 8];
    const float* mlp2_b1   = (const float*)d_in[base + 9];
    const float* mlp2_bn_g = (const float*)d_in[base + 10];
    const float* mlp2_bn_b = (const float*)d_in[base + 11];
    const float* mlp2_bn_m = (const float*)d_in[base + 12];
    const float* mlp2_bn_v = (const float*)d_in[base + 13];
    const float* mlp2_w2   = (const float*)d_in[base + 14];
    const float* mlp2_b2   = (const float*)d_in[base + 15];
    const float* out1_w    = (const float*)d_in[base + 16];
    const float* out1_b    = (const float*)d_in[base + 17];
    const float* out2_w    = (const float*)d_in[base + 18];
    const float* out2_b    = (const float*)d_in[base + 19];
    const float* out3_w    = (const float*)d_in[base + 20];
    const float* out3_b    = (const float*)d_in[base + 21];
    const float* out_w     = (const float*)d_in[base + 22];
    const float* out_b     = (const float*)d_in[base + 23];
    const float* eps1      = (const float*)d_in[base + 24];
    const float* eps2      = (const float*)d_in[base + 25];
    const float* eps3      = (const float*)d_in[base + 26];

    float* out = (float*)d_out;

    float *bufA, *bufB, *bufC, *z1, *alpha1, *beta1, *alpha2, *beta2;
    __half* wh;
    cudaGetSymbolAddress((void**)&bufA, g_bufA);
    cudaGetSymbolAddress((void**)&bufB, g_bufB);
    cudaGetSymbolAddress((void**)&bufC, g_bufC);
    cudaGetSymbolAddress((void**)&z1,   g_z1);
    cudaGetSymbolAddress((void**)&alpha1, g_alpha1);
    cudaGetSymbolAddress((void**)&beta1,  g_beta1);
    cudaGetSymbolAddress((void**)&alpha2, g_alpha2);
    cudaGetSymbolAddress((void**)&beta2,  g_beta2);
    cudaGetSymbolAddress((void**)&wh, g_Wh);

    cudaFuncSetAttribute(gemm_hmma_kernel<0>,
                         cudaFuncAttributeMaxDynamicSharedMemorySize, GSMEM);
    cudaFuncSetAttribute(gemm_hmma_kernel<1>,
                         cudaFuncAttributeMaxDynamicSharedMemorySize, GSMEM);

    dim3 ggrid(ceil_div(NN, BM), 2);   // (782, 2) = 1564 CTAs
    size_t wmat = (size_t)DD * WPITCH;

    // 1: fused setup
    setup_kernel<<<ceil_div(SETUP_TOTAL, 256), 256>>>(
        mlp1_w1, mlp1_w2, mlp2_w1, mlp2_w2, out1_w, out2_w, out3_w,
        mlp1_b1, mlp1_bn_g, mlp1_bn_b, mlp1_bn_m, mlp1_bn_v,
        mlp2_b1, mlp2_bn_g, mlp2_bn_b, mlp2_bn_m, mlp2_bn_v);

    // ---------- layer 1 ----------
    pad_scale_kernel<<<ceil_div(NN * XPITCH, 256), 256>>>(x, eps1);
    scatter_add_x_kernel<<<ceil_div(EE * (XPITCH / 4), 256), 256>>>(src, dst);
    gemm_hmma_kernel<0><<<ggrid, GTHREADS, GSMEM>>>(z1, XPITCH, 3, wh + 0 * wmat,
                                                    alpha1, beta1, bufA, nullptr, nullptr);
    gemm_hmma_kernel<0><<<ggrid, GTHREADS, GSMEM>>>(bufA, PITCH, 13, wh + 1 * wmat,
                                                    nullptr, mlp1_b2, bufB, nullptr, nullptr);
    // tanh: h1 -> bufA, (1+eps2)*h1 -> bufC
    gemm_hmma_kernel<1><<<ggrid, GTHREADS, GSMEM>>>(bufB, PITCH, 13, wh + 4 * wmat,
                                                    nullptr, out1_b, bufA, eps2, bufC);
    // ---------- layer 2 ----------
    scatter_add4_kernel<<<ceil_div(EE * (DD / 4), 256), 256>>>(bufA, src, dst, bufC);
    gemm_hmma_kernel<0><<<ggrid, GTHREADS, GSMEM>>>(bufC, PITCH, 13, wh + 2 * wmat,
                                                    alpha2, beta2, bufB, nullptr, nullptr);
    gemm_hmma_kernel<0><<<ggrid, GTHREADS, GSMEM>>>(bufB, PITCH, 13, wh + 3 * wmat,
                                                    nullptr, mlp2_b2, bufA, nullptr, nullptr);
    // tanh: h2 -> bufB, (1+eps3)*h2 -> bufC
    gemm_hmma_kernel<1><<<ggrid, GTHREADS, GSMEM>>>(bufA, PITCH, 13, wh + 5 * wmat,
                                                    nullptr, out2_b, bufB, eps3, bufC);
    // ---------- layer 3 ----------
    scatter_add4_kernel<<<ceil_div(EE * (DD / 4), 256), 256>>>(bufB, src, dst, bufC);
    gemm_hmma_kernel<0><<<ggrid, GTHREADS, GSMEM>>>(bufC, PITCH, 13, wh + 2 * wmat,
                                                    alpha2, beta2, bufA, nullptr, nullptr);
    gemm_hmma_kernel<0><<<ggrid, GTHREADS, GSMEM>>>(bufA, PITCH, 13, wh + 3 * wmat,
                                                    nullptr, mlp2_b2, bufB, nullptr, nullptr);
    gemm_hmma_kernel<1><<<ggrid, GTHREADS, GSMEM>>>(bufB, PITCH, 13, wh + 6 * wmat,
                                                    nullptr, out3_b, bufA, nullptr, nullptr);
    // ---------- pooling + output ----------
    pool_out_kernel<<<GG, 256>>>(bufA, batch, out_w, out_b, out);
    (void)n_in; (void)out_size;
}